// round 2
// baseline (speedup 1.0000x reference)
#include <cuda_runtime.h>

// Fused 3-phase LSTM (cent H=32 x100, enc H=64 x20, dec H=96 x30).
// Persistent CTA: 64 batch rows, weights + dup'd h-state in SMEM, c in regs.
// fp32 matmuls via fma.rn.f32x2: gate pairs (i,f)/(g,o) packed in lanes;
// h stored DUPLICATED (h,h) so one LDS.128 gives two packed operands (no movs).

#define TPB 1024
#define BT  64

typedef unsigned long long ull;

// ---------------- packed f32x2 helpers ----------------
__device__ __forceinline__ ull pk2(float lo, float hi) {
    ull r; asm("mov.b64 %0, {%1, %2};" : "=l"(r) : "f"(lo), "f"(hi)); return r;
}
__device__ __forceinline__ ull fma2(ull a, ull b, ull c) {
    ull d; asm("fma.rn.f32x2 %0, %1, %2, %3;" : "=l"(d) : "l"(a), "l"(b), "l"(c)); return d;
}
__device__ __forceinline__ float2 upk(ull a) {
    float lo, hi; asm("mov.b64 {%0, %1}, %2;" : "=f"(lo), "=f"(hi) : "l"(a));
    return make_float2(lo, hi);
}

// ---------------- fast activations ----------------
__device__ __forceinline__ float fex2(float x){ float r; asm("ex2.approx.f32 %0, %1;" : "=f"(r) : "f"(x)); return r; }
__device__ __forceinline__ float frcp(float x){ float r; asm("rcp.approx.f32 %0, %1;" : "=f"(r) : "f"(x)); return r; }
__device__ __forceinline__ float sigm(float x){
    return frcp(1.0f + fex2(-1.4426950408889634f * x));   // rcp(inf)=0 -> robust
}
__device__ __forceinline__ float tanh_(float x){
    return fmaf(2.0f, sigm(2.0f * x), -1.0f);
}

// ---------------- SMEM layout (float offsets) ----------------
// Ws:   gate-interleaved weights Ws[k*(4H) + j*4 + g], max 96*384 = 36864
// Cs:   c staging, ALIASED into Ws[16384..22528) — free during phases 1/2
//       (their W needs <=16384 floats); decoder reads Cs BEFORE load_W<96>.
// Hs2:  duplicated h state: [96 rows][64 batch][2 dup]  = 12288
// Xs2:  duplicated x staging: [64 batch][2 comp] ull     = 256 floats
#define WS_OFF    0
#define CS_OFF    16384
#define HS_OFF    36864
#define XS_OFF    49152
#define BPK_OFF   49408    // packed bias: [H][2] ull (max 192 ull = 384 f)
#define IPK_OFF   49792    // packed Wih:  [H][2][2] ull (max 256 ull = 512 f)
#define WEMB_OFF  50304    // 96 float2
#define BEMB_OFF  50496
#define SMEM_FLOATS 50500
#define SMEM_BYTES  (SMEM_FLOATS * 4)

#define HROW 128           // dup'd h row stride in floats

// ---------------- weight/bias staging ----------------
template<int H>
__device__ __forceinline__ void load_W(float* __restrict__ Ws,
                                       const float* __restrict__ Whh,
                                       const float* __restrict__ Wih, int tid)
{
    constexpr int total = 4 * H * H;
    for (int s = tid; s < total; s += TPB) {
        int row = s / H;
        int k   = s - row * H;
        int g   = row / H;
        int j   = row - g * H;
        float v = Whh[s];
        if (Wih) v += Wih[s];
        Ws[k * (4 * H) + j * 4 + g] = v;
    }
}

template<int H>
__device__ __forceinline__ void load_bias(ull* __restrict__ Bpk,
                                          const float* __restrict__ bih,
                                          const float* __restrict__ bhh, int tid)
{
    for (int j = tid; j < H; j += TPB) {
        Bpk[j * 2 + 0] = pk2(bih[j] + bhh[j],             bih[H + j] + bhh[H + j]);
        Bpk[j * 2 + 1] = pk2(bih[2*H + j] + bhh[2*H + j], bih[3*H + j] + bhh[3*H + j]);
    }
}

template<int H>
__device__ __forceinline__ void load_ih(ull* __restrict__ Ipk,
                                        const float* __restrict__ Wih, int tid)
{
    for (int t = tid; t < 2 * H; t += TPB) {
        int j = t >> 1, inp = t & 1;
        Ipk[(j * 2 + inp) * 2 + 0] = pk2(Wih[(0*H + j) * 2 + inp], Wih[(1*H + j) * 2 + inp]);
        Ipk[(j * 2 + inp) * 2 + 1] = pk2(Wih[(2*H + j) * 2 + inp], Wih[(3*H + j) * 2 + inp]);
    }
}

// ---------------- gate matmul: gates += h @ W^T ----------------
// Hrows points to dup'd h rows; thread covers cells (j0..j0+NH-1, b0..b0+1).
template<int H, int NH>
__device__ __forceinline__ void gates_mm(const float* __restrict__ Ws,
                                         const float* __restrict__ Hrows,
                                         int j0, int lane,
                                         ull (&aif)[NH][2], ull (&ago)[NH][2])
{
    const float* wb = Ws + j0 * 4;
    const float* hb = Hrows + lane * 4;          // dup'd pair of 2 cells = 16B
    #pragma unroll 4
    for (int k = 0; k < H; k++) {
        ulonglong2 hp = *(const ulonglong2*)(hb + k * HROW);   // (h0,h0),(h1,h1)
        #pragma unroll
        for (int i = 0; i < NH; i++) {
            ulonglong2 w = *(const ulonglong2*)(wb + k * (4 * H) + i * 4); // bcast
            aif[i][0] = fma2(w.x, hp.x, aif[i][0]);
            ago[i][0] = fma2(w.y, hp.x, ago[i][0]);
            aif[i][1] = fma2(w.x, hp.y, aif[i][1]);
            ago[i][1] = fma2(w.y, hp.y, ago[i][1]);
        }
    }
}

// ---------------- activations + state update (writes dup'd h) ----------------
template<int NH>
__device__ __forceinline__ void act_update(ull (&aif)[NH][2], ull (&ago)[NH][2],
                                           float (&cr)[NH][2],
                                           float* __restrict__ Hw, int lane)
{
    #pragma unroll
    for (int i = 0; i < NH; i++) {
        float hn[2];
        #pragma unroll
        for (int b = 0; b < 2; b++) {
            float2 sif = upk(aif[i][b]);
            float2 sgo = upk(ago[i][b]);
            float ig = sigm(sif.x);
            float fg = sigm(sif.y);
            float gg = tanh_(sgo.x);
            float og = sigm(sgo.y);
            float cn = fmaf(fg, cr[i][b], ig * gg);
            cr[i][b] = cn;
            hn[b] = og * tanh_(cn);
        }
        *(float4*)(Hw + i * HROW + lane * 4) = make_float4(hn[0], hn[0], hn[1], hn[1]);
    }
}

// ---------------- input-driven LSTM phase (cent / enc) ----------------
template<int H, int NH, int HOFF, int T>
__device__ __forceinline__ void lstm_io_phase(float* __restrict__ S,
                                              const float* __restrict__ xsrc, int xstride,
                                              int B, int bbase, int tid)
{
    float* Ws  = S + WS_OFF;
    float* Hs  = S + HS_OFF;
    float* Cs  = S + CS_OFF;
    ull*   Xs2 = (ull*)(S + XS_OFF);
    ull*   Bpk = (ull*)(S + BPK_OFF);
    ull*   Ipk = (ull*)(S + IPK_OFF);

    static_assert((H / NH) * 32 == TPB, "thread map");
    int hg = tid >> 5, lane = tid & 31;
    int j0 = hg * NH, b0 = lane * 2;

    float cr[NH][2];
    #pragma unroll
    for (int i = 0; i < NH; i++) { cr[i][0] = 0.0f; cr[i][1] = 0.0f; }

    ull bif[NH], bgo[NH], wif0[NH], wif1[NH], wgo0[NH], wgo1[NH];
    #pragma unroll
    for (int i = 0; i < NH; i++) {
        bif[i]  = Bpk[(j0 + i) * 2 + 0];
        bgo[i]  = Bpk[(j0 + i) * 2 + 1];
        wif0[i] = Ipk[((j0 + i) * 2 + 0) * 2 + 0];
        wgo0[i] = Ipk[((j0 + i) * 2 + 0) * 2 + 1];
        wif1[i] = Ipk[((j0 + i) * 2 + 1) * 2 + 0];
        wgo1[i] = Ipk[((j0 + i) * 2 + 1) * 2 + 1];
    }

    const float* Hrows = Hs + HOFF * HROW;
    float*       Hw    = Hs + (HOFF + j0) * HROW;

    int bb = bbase + tid; if (bb >= B) bb = B - 1;   // for x staging (tid<64)

    for (int t = 0; t < T; t++) {
        // prefetch next x early so LDG latency hides under gates_mm
        float2 xn;
        bool stage = (tid < BT) && (t + 1 < T);
        if (stage)
            xn = *(const float2*)&xsrc[(size_t)bb * xstride + (size_t)(t + 1) * 2];

        ull aif[NH][2], ago[NH][2];
        // x contribution (dup'd x pairs from SMEM: one LDS.128 per cell)
        ulonglong2 xc0 = *(const ulonglong2*)(Xs2 + 2 * b0);
        ulonglong2 xc1 = *(const ulonglong2*)(Xs2 + 2 * b0 + 2);
        #pragma unroll
        for (int i = 0; i < NH; i++) {
            aif[i][0] = fma2(wif0[i], xc0.x, fma2(wif1[i], xc0.y, bif[i]));
            ago[i][0] = fma2(wgo0[i], xc0.x, fma2(wgo1[i], xc0.y, bgo[i]));
            aif[i][1] = fma2(wif0[i], xc1.x, fma2(wif1[i], xc1.y, bif[i]));
            ago[i][1] = fma2(wgo0[i], xc1.x, fma2(wgo1[i], xc1.y, bgo[i]));
        }
        gates_mm<H, NH>(Ws, Hrows, j0, lane, aif, ago);
        __syncthreads();                    // all h + x reads done
        act_update<NH>(aif, ago, cr, Hw, lane);
        if (stage) {
            Xs2[2 * tid + 0] = pk2(xn.x, xn.x);
            Xs2[2 * tid + 1] = pk2(xn.y, xn.y);
        }
        __syncthreads();                    // new h + x visible
    }

    // stage final c for the decoder (Cs aliased into free Ws space)
    #pragma unroll
    for (int i = 0; i < NH; i++) {
        Cs[(HOFF + j0 + i) * BT + b0 + 0] = cr[i][0];
        Cs[(HOFF + j0 + i) * BT + b0 + 1] = cr[i][1];
    }
}

// ---------------- main fused kernel ----------------
__global__ void __launch_bounds__(TPB, 1)
lstm_fused_kernel(const float* __restrict__ traj,   // [B,20,2]
                  const float* __restrict__ cl,     // [B,100,2]
                  const float* __restrict__ Wih_c, const float* __restrict__ Whh_c,
                  const float* __restrict__ bih_c, const float* __restrict__ bhh_c,
                  const float* __restrict__ Wih_e, const float* __restrict__ Whh_e,
                  const float* __restrict__ bih_e, const float* __restrict__ bhh_e,
                  const float* __restrict__ Wih_d, const float* __restrict__ Whh_d,
                  const float* __restrict__ bih_d, const float* __restrict__ bhh_d,
                  const float* __restrict__ W_emb, const float* __restrict__ b_emb,
                  float* __restrict__ out, int B)
{
    extern __shared__ float S[];
    int tid   = threadIdx.x;
    int bbase = blockIdx.x * BT;

    float*  Ws   = S + WS_OFF;
    float*  Hs   = S + HS_OFF;
    float*  Cs   = S + CS_OFF;
    ull*    Xs2  = (ull*)(S + XS_OFF);
    ull*    Bpk  = (ull*)(S + BPK_OFF);
    float2* Wemb = (float2*)(S + WEMB_OFF);
    float2* Bemb = (float2*)(S + BEMB_OFF);

    // zero dup'd h buffer (initial states)
    for (int s = tid; s < 96 * HROW; s += TPB) Hs[s] = 0.0f;

    int bbc = bbase + tid; if (bbc >= B) bbc = B - 1;

    // ---- phase 1: centerline LSTM (H=32) -> rows 64..95 ----
    load_W<32>(Ws, Whh_c, nullptr, tid);
    load_bias<32>(Bpk, bih_c, bhh_c, tid);
    load_ih<32>((ull*)(S + IPK_OFF), Wih_c, tid);
    if (tid < BT) {
        float2 x = *(const float2*)&cl[(size_t)bbc * 200];
        Xs2[2 * tid + 0] = pk2(x.x, x.x);
        Xs2[2 * tid + 1] = pk2(x.y, x.y);
    }
    __syncthreads();
    lstm_io_phase<32, 1, 64, 100>(S, cl, 200, B, bbase, tid);
    __syncthreads();

    // ---- phase 2: encoder LSTM (H=64) -> rows 0..63 ----
    load_W<64>(Ws, Whh_e, nullptr, tid);
    load_bias<64>(Bpk, bih_e, bhh_e, tid);
    load_ih<64>((ull*)(S + IPK_OFF), Wih_e, tid);
    if (tid < BT) {
        float2 x = *(const float2*)&traj[(size_t)bbc * 40];
        Xs2[2 * tid + 0] = pk2(x.x, x.x);
        Xs2[2 * tid + 1] = pk2(x.y, x.y);
    }
    __syncthreads();
    lstm_io_phase<64, 2, 0, 20>(S, traj, 40, B, bbase, tid);
    __syncthreads();

    // ---- phase 3: decoder (H=96), x == h so Wih+Whh fold into one matrix ----
    {
        constexpr int NH = 3;
        int hg = tid >> 5, lane = tid & 31;
        int j0 = hg * NH, b0 = lane * 2;

        // read c BEFORE load_W<96> clobbers the aliased Cs region
        float cr[NH][2];
        #pragma unroll
        for (int i = 0; i < NH; i++) {
            cr[i][0] = Cs[(j0 + i) * BT + b0 + 0];
            cr[i][1] = Cs[(j0 + i) * BT + b0 + 1];
        }
        __syncthreads();

        load_W<96>(Ws, Whh_d, Wih_d, tid);
        load_bias<96>(Bpk, bih_d, bhh_d, tid);
        for (int k = tid; k < 96; k += TPB) Wemb[k] = make_float2(W_emb[k], W_emb[96 + k]);
        if (tid == 0) *Bemb = make_float2(b_emb[0], b_emb[1]);
        __syncthreads();

        ull bif[NH], bgo[NH];
        #pragma unroll
        for (int i = 0; i < NH; i++) {
            bif[i] = Bpk[(j0 + i) * 2 + 0];
            bgo[i] = Bpk[(j0 + i) * 2 + 1];
        }

        float* Hw = Hs + j0 * HROW;

        for (int t = 0; t < 30; t++) {
            ull aif[NH][2], ago[NH][2];
            #pragma unroll
            for (int i = 0; i < NH; i++) {
                aif[i][0] = bif[i]; aif[i][1] = bif[i];
                ago[i][0] = bgo[i]; ago[i][1] = bgo[i];
            }
            gates_mm<96, NH>(Ws, Hs, j0, lane, aif, ago);
            __syncthreads();                 // all h reads done
            act_update<NH>(aif, ago, cr, Hw, lane);
            __syncthreads();                 // new h visible

            // projection: pos = h_new @ W_emb^T + b_emb (64 threads; overlaps
            // with other warps' next gates_mm; safe: next h-write is after the
            // next mid-step barrier which these threads gate)
            if (tid < BT) {
                float2 acc = *Bemb;
                #pragma unroll 8
                for (int k = 0; k < 96; k++) {
                    ull hp = *(const ull*)(Hs + k * HROW + 2 * tid); // dup'd pair
                    float h = upk(hp).x;
                    float2 w = Wemb[k];
                    acc.x = fmaf(h, w.x, acc.x);
                    acc.y = fmaf(h, w.y, acc.y);
                }
                int bb = bbase + tid;
                if (bb < B) *(float2*)&out[(size_t)(bb * 30 + t) * 2] = acc;
            }
        }
    }
}

extern "C" void kernel_launch(void* const* d_in, const int* in_sizes, int n_in,
                              void* d_out, int out_size)
{
    const float* traj  = (const float*)d_in[0];
    const float* cl    = (const float*)d_in[1];
    const float* Wih_c = (const float*)d_in[2];
    const float* Whh_c = (const float*)d_in[3];
    const float* bih_c = (const float*)d_in[4];
    const float* bhh_c = (const float*)d_in[5];
    const float* Wih_e = (const float*)d_in[6];
    const float* Whh_e = (const float*)d_in[7];
    const float* bih_e = (const float*)d_in[8];
    const float* bhh_e = (const float*)d_in[9];
    const float* Wih_d = (const float*)d_in[10];
    const float* Whh_d = (const float*)d_in[11];
    const float* bih_d = (const float*)d_in[12];
    const float* bhh_d = (const float*)d_in[13];
    const float* W_emb = (const float*)d_in[14];
    const float* b_emb = (const float*)d_in[15];

    int B = in_sizes[0] / 40;
    int grid = (B + BT - 1) / BT;

    cudaFuncSetAttribute(lstm_fused_kernel,
                         cudaFuncAttributeMaxDynamicSharedMemorySize, SMEM_BYTES);
    lstm_fused_kernel<<<grid, TPB, SMEM_BYTES>>>(
        traj, cl, Wih_c, Whh_c, bih_c, bhh_c,
        Wih_e, Whh_e, bih_e, bhh_e,
        Wih_d, Whh_d, bih_d, bhh_d,
        W_emb, b_emb, (float*)d_out, B);
}

// round 3
// speedup vs baseline: 1.0999x; 1.0999x over previous
#include <cuda_runtime.h>

// Fused 3-phase LSTM (cent H=32 x100, enc H=64 x20, dec H=96 x30).
// Persistent CTA: 64 batch rows, weights + h in SMEM, c in regs.
// fp32 matmuls via fma.rn.f32x2 (gate pairs (i,f)/(g,o) packed per lane).
// R3: double-buffered h/x (1 barrier/step) + batch-split halves so the
// MUFU activation burst of half A overlaps the FFMA2 stream of half B.

#define TPB 512
#define BT  64

typedef unsigned long long ull;

// ---------------- packed f32x2 helpers ----------------
__device__ __forceinline__ ull pk2(float lo, float hi) {
    ull r; asm("mov.b64 %0, {%1, %2};" : "=l"(r) : "f"(lo), "f"(hi)); return r;
}
__device__ __forceinline__ ull fma2(ull a, ull b, ull c) {
    ull d; asm("fma.rn.f32x2 %0, %1, %2, %3;" : "=l"(d) : "l"(a), "l"(b), "l"(c)); return d;
}
__device__ __forceinline__ float2 upk(ull a) {
    float lo, hi; asm("mov.b64 {%0, %1}, %2;" : "=f"(lo), "=f"(hi) : "l"(a));
    return make_float2(lo, hi);
}

// ---------------- fast activations ----------------
__device__ __forceinline__ float fex2(float x){ float r; asm("ex2.approx.f32 %0, %1;" : "=f"(r) : "f"(x)); return r; }
__device__ __forceinline__ float frcp(float x){ float r; asm("rcp.approx.f32 %0, %1;" : "=f"(r) : "f"(x)); return r; }
__device__ __forceinline__ float sigm(float x){
    return frcp(1.0f + fex2(-1.4426950408889634f * x));   // rcp(inf)=0 -> robust
}
__device__ __forceinline__ float tanh_(float x){
    return fmaf(2.0f, sigm(2.0f * x), -1.0f);
}

// ---------------- SMEM layout (float offsets) ----------------
#define WS_OFF    0        // gate-interleaved weights Ws[k*(4H)+j*4+g], max 36864
#define CS_OFF    16384    // c staging ALIASED into Ws (phases 1/2 use <=16384)
#define HS_OFF    36864    // h state, 2 buffers of [96 rows][64]: 2*6144
#define XS_OFF    49152    // x staging dup'd: 2 buffers of 64*2 ull = 2*256 floats
#define BPK_OFF   49664    // packed bias: [H][2] ull (max 192 ull)
#define IPK_OFF   50048    // packed Wih: [H][2][2] ull (max 256 ull)
#define WEMB_OFF  50560    // 96 float2
#define BEMB_OFF  50752
#define SMEM_FLOATS 50756
#define SMEM_BYTES  (SMEM_FLOATS * 4)

// ---------------- weight/bias staging ----------------
template<int H>
__device__ __forceinline__ void load_W(float* __restrict__ Ws,
                                       const float* __restrict__ Whh,
                                       const float* __restrict__ Wih, int tid)
{
    constexpr int total = 4 * H * H;
    for (int s = tid; s < total; s += TPB) {
        int row = s / H;
        int k   = s - row * H;
        int g   = row / H;
        int j   = row - g * H;
        float v = Whh[s];
        if (Wih) v += Wih[s];
        Ws[k * (4 * H) + j * 4 + g] = v;
    }
}

template<int H>
__device__ __forceinline__ void load_bias(ull* __restrict__ Bpk,
                                          const float* __restrict__ bih,
                                          const float* __restrict__ bhh, int tid)
{
    for (int j = tid; j < H; j += TPB) {
        Bpk[j * 2 + 0] = pk2(bih[j] + bhh[j],             bih[H + j] + bhh[H + j]);
        Bpk[j * 2 + 1] = pk2(bih[2*H + j] + bhh[2*H + j], bih[3*H + j] + bhh[3*H + j]);
    }
}

template<int H>
__device__ __forceinline__ void load_ih(ull* __restrict__ Ipk,
                                        const float* __restrict__ Wih, int tid)
{
    for (int t = tid; t < 2 * H; t += TPB) {
        int j = t >> 1, inp = t & 1;
        Ipk[(j * 2 + inp) * 2 + 0] = pk2(Wih[(0*H + j) * 2 + inp], Wih[(1*H + j) * 2 + inp]);
        Ipk[(j * 2 + inp) * 2 + 1] = pk2(Wih[(2*H + j) * 2 + inp], Wih[(3*H + j) * 2 + inp]);
    }
}

// ---------------- half-tile gate matmul: gates += h @ W^T ----------------
template<int H, int NH, int NBH>
__device__ __forceinline__ void half_gates(const float* __restrict__ Ws,
                                           const float* __restrict__ Hrows,
                                           int j0, int b0h,
                                           ull (&aif)[NH][NBH], ull (&ago)[NH][NBH])
{
    const float* wb = Ws + j0 * 4;
    const float* hb = Hrows + b0h;
    #pragma unroll 8
    for (int k = 0; k < H; k++) {
        ull hp[NBH];
        if constexpr (NBH == 2) {
            float2 hv = *(const float2*)(hb + k * BT);
            hp[0] = pk2(hv.x, hv.x); hp[1] = pk2(hv.y, hv.y);
        } else {
            float hv = hb[k * BT];
            hp[0] = pk2(hv, hv);
        }
        #pragma unroll
        for (int i = 0; i < NH; i++) {
            ulonglong2 w = *(const ulonglong2*)(wb + k * (4 * H) + i * 4);
            #pragma unroll
            for (int b = 0; b < NBH; b++) {
                aif[i][b] = fma2(w.x, hp[b], aif[i][b]);
                ago[i][b] = fma2(w.y, hp[b], ago[i][b]);
            }
        }
    }
}

// ---------------- half-tile activations + h store (non-dup layout) ----------------
template<int NH, int NBH>
__device__ __forceinline__ void half_act(ull (&aif)[NH][NBH], ull (&ago)[NH][NBH],
                                         float (&cr)[NH][NBH],
                                         float* __restrict__ Hw, int b0h)
{
    #pragma unroll
    for (int i = 0; i < NH; i++) {
        float hn[NBH];
        #pragma unroll
        for (int b = 0; b < NBH; b++) {
            float2 sif = upk(aif[i][b]);
            float2 sgo = upk(ago[i][b]);
            float ig = sigm(sif.x);
            float fg = sigm(sif.y);
            float gg = tanh_(sgo.x);
            float og = sigm(sgo.y);
            float cn = fmaf(fg, cr[i][b], ig * gg);
            cr[i][b] = cn;
            hn[b] = og * tanh_(cn);
        }
        if constexpr (NBH == 2)
            *(float2*)(Hw + i * BT + b0h) = make_float2(hn[0], hn[1]);
        else
            Hw[i * BT + b0h] = hn[0];
    }
}

// ---------------- half-tile x contribution + bias init ----------------
template<int NH, int NBH>
__device__ __forceinline__ void half_init_x(const ull* __restrict__ Xc, int b0h,
                                            const ull* bif, const ull* bgo,
                                            const ull* wif0, const ull* wif1,
                                            const ull* wgo0, const ull* wgo1,
                                            ull (&aif)[NH][NBH], ull (&ago)[NH][NBH])
{
    #pragma unroll
    for (int b = 0; b < NBH; b++) {
        ull x0 = Xc[2 * (b0h + b) + 0];
        ull x1 = Xc[2 * (b0h + b) + 1];
        #pragma unroll
        for (int i = 0; i < NH; i++) {
            aif[i][b] = fma2(wif0[i], x0, fma2(wif1[i], x1, bif[i]));
            ago[i][b] = fma2(wgo0[i], x0, fma2(wgo1[i], x1, bgo[i]));
        }
    }
}

// ---------------- input-driven LSTM phase (cent / enc) ----------------
// NB = per-thread batch tile (split into 2 halves of NBH = NB/2).
template<int H, int NH, int NB, int HOFF, int T>
__device__ __forceinline__ void lstm_io_phase(float* __restrict__ S,
                                              const float* __restrict__ xsrc, int xstride,
                                              int B, int bbase, int tid)
{
    constexpr int NBH = NB / 2;
    constexpr int BG  = BT / NB;
    static_assert((H / NH) * BG == TPB, "thread map");

    float* Ws  = S + WS_OFF;
    float* Cs  = S + CS_OFF;
    ull*   Bpk = (ull*)(S + BPK_OFF);
    ull*   Ipk = (ull*)(S + IPK_OFF);

    int hg = tid / BG;
    int bg = tid % BG;
    int j0 = hg * NH, b0 = bg * NB;

    float crA[NH][NBH], crB[NH][NBH];
    #pragma unroll
    for (int i = 0; i < NH; i++)
        #pragma unroll
        for (int b = 0; b < NBH; b++) { crA[i][b] = 0.0f; crB[i][b] = 0.0f; }

    ull bif[NH], bgo[NH], wif0[NH], wif1[NH], wgo0[NH], wgo1[NH];
    #pragma unroll
    for (int i = 0; i < NH; i++) {
        bif[i]  = Bpk[(j0 + i) * 2 + 0];
        bgo[i]  = Bpk[(j0 + i) * 2 + 1];
        wif0[i] = Ipk[((j0 + i) * 2 + 0) * 2 + 0];
        wgo0[i] = Ipk[((j0 + i) * 2 + 0) * 2 + 1];
        wif1[i] = Ipk[((j0 + i) * 2 + 1) * 2 + 0];
        wgo1[i] = Ipk[((j0 + i) * 2 + 1) * 2 + 1];
    }

    float* H0 = S + HS_OFF;          // buffer 0
    float* H1 = S + HS_OFF + 6144;   // buffer 1
    ull*   X0 = (ull*)(S + XS_OFF);
    ull*   X1 = (ull*)(S + XS_OFF) + 128;

    int bb = bbase + tid; if (bb >= B) bb = B - 1;   // x staging (tid<64)

    float* Hc = H0; float* Hn = H1;
    ull*   Xc = X0; ull*   Xn = X1;

    for (int t = 0; t < T; t++) {
        // prefetch next x early (LDG hides under the fma stream)
        float2 xn;
        bool stage = (tid < BT) && (t + 1 < T);
        if (stage)
            xn = *(const float2*)&xsrc[(size_t)bb * xstride + (size_t)(t + 1) * 2];

        const float* Hrows = Hc + HOFF * BT;
        float*       Hw    = Hn + (HOFF + j0) * BT;

        // half A
        ull aifA[NH][NBH], agoA[NH][NBH];
        half_init_x<NH,NBH>(Xc, b0, bif, bgo, wif0, wif1, wgo0, wgo1, aifA, agoA);
        half_gates<H,NH,NBH>(Ws, Hrows, j0, b0, aifA, agoA);
        // half B (independent of half A's MUFU chain -> overlap)
        ull aifB[NH][NBH], agoB[NH][NBH];
        half_init_x<NH,NBH>(Xc, b0 + NBH, bif, bgo, wif0, wif1, wgo0, wgo1, aifB, agoB);
        half_act<NH,NBH>(aifA, agoA, crA, Hw, b0);
        half_gates<H,NH,NBH>(Ws, Hrows, j0, b0 + NBH, aifB, agoB);
        half_act<NH,NBH>(aifB, agoB, crB, Hw, b0 + NBH);

        if (stage) {
            Xn[2 * tid + 0] = pk2(xn.x, xn.x);
            Xn[2 * tid + 1] = pk2(xn.y, xn.y);
        }
        __syncthreads();                 // one barrier per step
        { float* tf = Hc; Hc = Hn; Hn = tf; }
        { ull*  tx = Xc; Xc = Xn; Xn = tx; }
    }
    // T even -> final h landed back in buffer 0 (= decoder's read buffer)

    // stage final c for the decoder (Cs aliased into free Ws space)
    #pragma unroll
    for (int i = 0; i < NH; i++)
        #pragma unroll
        for (int b = 0; b < NBH; b++) {
            Cs[(HOFF + j0 + i) * BT + b0 + b]       = crA[i][b];
            Cs[(HOFF + j0 + i) * BT + b0 + NBH + b] = crB[i][b];
        }
}

// ---------------- main fused kernel ----------------
__global__ void __launch_bounds__(TPB, 1)
lstm_fused_kernel(const float* __restrict__ traj,   // [B,20,2]
                  const float* __restrict__ cl,     // [B,100,2]
                  const float* __restrict__ Wih_c, const float* __restrict__ Whh_c,
                  const float* __restrict__ bih_c, const float* __restrict__ bhh_c,
                  const float* __restrict__ Wih_e, const float* __restrict__ Whh_e,
                  const float* __restrict__ bih_e, const float* __restrict__ bhh_e,
                  const float* __restrict__ Wih_d, const float* __restrict__ Whh_d,
                  const float* __restrict__ bih_d, const float* __restrict__ bhh_d,
                  const float* __restrict__ W_emb, const float* __restrict__ b_emb,
                  float* __restrict__ out, int B)
{
    extern __shared__ float S[];
    int tid   = threadIdx.x;
    int bbase = blockIdx.x * BT;

    float*  Ws   = S + WS_OFF;
    float*  Cs   = S + CS_OFF;
    float*  H0   = S + HS_OFF;
    float*  H1   = S + HS_OFF + 6144;
    ull*    X0   = (ull*)(S + XS_OFF);
    ull*    Bpk  = (ull*)(S + BPK_OFF);
    float2* Wemb = (float2*)(S + WEMB_OFF);
    float2* Bemb = (float2*)(S + BEMB_OFF);

    // zero h buffer 0 (initial states; each phase only reads its own rows at t=0)
    for (int s = tid; s < 6144; s += TPB) H0[s] = 0.0f;

    int bbc = bbase + tid; if (bbc >= B) bbc = B - 1;

    // ---- phase 1: centerline LSTM (H=32) -> rows 64..95 ----
    load_W<32>(Ws, Whh_c, nullptr, tid);
    load_bias<32>(Bpk, bih_c, bhh_c, tid);
    load_ih<32>((ull*)(S + IPK_OFF), Wih_c, tid);
    if (tid < BT) {
        float2 x = *(const float2*)&cl[(size_t)bbc * 200];
        X0[2 * tid + 0] = pk2(x.x, x.x);
        X0[2 * tid + 1] = pk2(x.y, x.y);
    }
    __syncthreads();
    lstm_io_phase<32, 2, 2, 64, 100>(S, cl, 200, B, bbase, tid);
    __syncthreads();

    // ---- phase 2: encoder LSTM (H=64) -> rows 0..63 ----
    load_W<64>(Ws, Whh_e, nullptr, tid);
    load_bias<64>(Bpk, bih_e, bhh_e, tid);
    load_ih<64>((ull*)(S + IPK_OFF), Wih_e, tid);
    if (tid < BT) {
        float2 x = *(const float2*)&traj[(size_t)bbc * 40];
        X0[2 * tid + 0] = pk2(x.x, x.x);
        X0[2 * tid + 1] = pk2(x.y, x.y);
    }
    __syncthreads();
    lstm_io_phase<64, 2, 4, 0, 20>(S, traj, 40, B, bbase, tid);
    __syncthreads();

    // ---- phase 3: decoder (H=96), x == h so Wih+Whh fold into one matrix ----
    {
        constexpr int NH = 3, NB = 4, NBH = 2, BG = BT / NB;
        int hg = tid / BG, bg = tid % BG;
        int j0 = hg * NH, b0 = bg * NB;

        // read c BEFORE load_W<96> clobbers the aliased Cs region
        float crA[NH][NBH], crB[NH][NBH];
        #pragma unroll
        for (int i = 0; i < NH; i++)
            #pragma unroll
            for (int b = 0; b < NBH; b++) {
                crA[i][b] = Cs[(j0 + i) * BT + b0 + b];
                crB[i][b] = Cs[(j0 + i) * BT + b0 + NBH + b];
            }
        __syncthreads();

        load_W<96>(Ws, Whh_d, Wih_d, tid);
        load_bias<96>(Bpk, bih_d, bhh_d, tid);
        for (int k = tid; k < 96; k += TPB) Wemb[k] = make_float2(W_emb[k], W_emb[96 + k]);
        if (tid == 0) *Bemb = make_float2(b_emb[0], b_emb[1]);
        __syncthreads();

        ull bif[NH], bgo[NH];
        #pragma unroll
        for (int i = 0; i < NH; i++) {
            bif[i] = Bpk[(j0 + i) * 2 + 0];
            bgo[i] = Bpk[(j0 + i) * 2 + 1];
        }

        float* Hc = H0; float* Hn = H1;   // h0 = concat(enc, cent) sits in H0

        for (int t = 0; t < 30; t++) {
            float* Hw = Hn + j0 * BT;

            ull aifA[NH][NBH], agoA[NH][NBH];
            #pragma unroll
            for (int i = 0; i < NH; i++)
                #pragma unroll
                for (int b = 0; b < NBH; b++) { aifA[i][b] = bif[i]; agoA[i][b] = bgo[i]; }
            half_gates<96,NH,NBH>(Ws, Hc, j0, b0, aifA, agoA);

            ull aifB[NH][NBH], agoB[NH][NBH];
            #pragma unroll
            for (int i = 0; i < NH; i++)
                #pragma unroll
                for (int b = 0; b < NBH; b++) { aifB[i][b] = bif[i]; agoB[i][b] = bgo[i]; }
            half_act<NH,NBH>(aifA, agoA, crA, Hw, b0);
            half_gates<96,NH,NBH>(Ws, Hc, j0, b0 + NBH, aifB, agoB);
            half_act<NH,NBH>(aifB, agoB, crB, Hw, b0 + NBH);

            __syncthreads();                 // new h (in Hn) visible

            // projection: pos = h_new @ W_emb^T + b_emb
            // (64 threads; overlaps other warps' next-step gates. Safe: both
            // read Hn; next step's writes go to Hc.)
            if (tid < BT) {
                float2 acc = *Bemb;
                #pragma unroll 8
                for (int k = 0; k < 96; k++) {
                    float  h = Hn[k * BT + tid];
                    float2 w = Wemb[k];
                    acc.x = fmaf(h, w.x, acc.x);
                    acc.y = fmaf(h, w.y, acc.y);
                }
                int bb = bbase + tid;
                if (bb < B) *(float2*)&out[(size_t)(bb * 30 + t) * 2] = acc;
            }
            { float* tf = Hc; Hc = Hn; Hn = tf; }
        }
    }
}

extern "C" void kernel_launch(void* const* d_in, const int* in_sizes, int n_in,
                              void* d_out, int out_size)
{
    const float* traj  = (const float*)d_in[0];
    const float* cl    = (const float*)d_in[1];
    const float* Wih_c = (const float*)d_in[2];
    const float* Whh_c = (const float*)d_in[3];
    const float* bih_c = (const float*)d_in[4];
    const float* bhh_c = (const float*)d_in[5];
    const float* Wih_e = (const float*)d_in[6];
    const float* Whh_e = (const float*)d_in[7];
    const float* bih_e = (const float*)d_in[8];
    const float* bhh_e = (const float*)d_in[9];
    const float* Wih_d = (const float*)d_in[10];
    const float* Whh_d = (const float*)d_in[11];
    const float* bih_d = (const float*)d_in[12];
    const float* bhh_d = (const float*)d_in[13];
    const float* W_emb = (const float*)d_in[14];
    const float* b_emb = (const float*)d_in[15];

    int B = in_sizes[0] / 40;
    int grid = (B + BT - 1) / BT;

    cudaFuncSetAttribute(lstm_fused_kernel,
                         cudaFuncAttributeMaxDynamicSharedMemorySize, SMEM_BYTES);
    lstm_fused_kernel<<<grid, TPB, SMEM_BYTES>>>(
        traj, cl, Wih_c, Whh_c, bih_c, bhh_c,
        Wih_e, Whh_e, bih_e, bhh_e,
        Wih_d, Whh_d, bih_d, bhh_d,
        W_emb, b_emb, (float*)d_out, B);
}

// round 4
// speedup vs baseline: 1.1766x; 1.0697x over previous
#include <cuda_runtime.h>

// Fused 3-phase LSTM (cent H=32 x100, enc H=64 x20, dec H=96 x30).
// R4: batch columns are independent -> 4 warpgroups of 128 threads, each
// owning 16 batch columns, synced with NAMED barriers only (no CTA-wide
// lockstep). Groups are time-skewed (__nanosleep) so one group's MUFU
// activation burst overlaps the other groups' FFMA2 streams on each SMSP.
// h stored DUPLICATED (h,h) so the packed-f32x2 matmul needs zero movs.

#define TPB  512
#define BT   64
#define GB   16      // batch columns per warpgroup
#define HROW 128     // dup'd h row stride (floats)

typedef unsigned long long ull;

// ---------------- packed f32x2 helpers ----------------
__device__ __forceinline__ ull pk2(float lo, float hi) {
    ull r; asm("mov.b64 %0, {%1, %2};" : "=l"(r) : "f"(lo), "f"(hi)); return r;
}
__device__ __forceinline__ ull fma2(ull a, ull b, ull c) {
    ull d; asm("fma.rn.f32x2 %0, %1, %2, %3;" : "=l"(d) : "l"(a), "l"(b), "l"(c)); return d;
}
__device__ __forceinline__ float2 upk(ull a) {
    float lo, hi; asm("mov.b64 {%0, %1}, %2;" : "=f"(lo), "=f"(hi) : "l"(a));
    return make_float2(lo, hi);
}

// ---------------- fast activations (ex2-based, proven 7e-7 rel err) ----------------
__device__ __forceinline__ float fex2(float x){ float r; asm("ex2.approx.f32 %0, %1;" : "=f"(r) : "f"(x)); return r; }
__device__ __forceinline__ float frcp(float x){ float r; asm("rcp.approx.f32 %0, %1;" : "=f"(r) : "f"(x)); return r; }
__device__ __forceinline__ float sigm(float x){
    return frcp(1.0f + fex2(-1.4426950408889634f * x));
}
__device__ __forceinline__ float tanh_(float x){
    return fmaf(2.0f, sigm(2.0f * x), -1.0f);
}

// ---------------- named barrier per warpgroup ----------------
__device__ __forceinline__ void gbar(int g) {
    asm volatile("bar.sync %0, %1;" :: "r"(g + 1), "r"(128) : "memory");
}

// ---------------- SMEM layout (float offsets) ----------------
#define WS_OFF    0        // gate-interleaved weights Ws[k*(4H)+j*4+g], max 36864
#define CS_OFF    16384    // c staging [96][64], aliased into Ws (ph1/2 use <=16384)
#define HS_OFF    36864    // dup'd h: [96 rows][64 b][2 dup] = 12288
#define XS_OFF    49152    // dup'd x: [64 b][2 comp] ull = 256 floats
#define BPK_OFF   49408    // packed bias: [H][2] ull (max 192 ull)
#define IPK_OFF   49792    // packed Wih:  [H][2][2] ull (max 256 ull)
#define WEMB_OFF  50304    // 96 float2
#define BEMB_OFF  50496
#define SMEM_FLOATS 50498
#define SMEM_BYTES  (SMEM_FLOATS * 4)

// ---------------- weight/bias staging (CTA-wide) ----------------
template<int H>
__device__ __forceinline__ void load_W(float* __restrict__ Ws,
                                       const float* __restrict__ Whh,
                                       const float* __restrict__ Wih, int tid)
{
    constexpr int total = 4 * H * H;
    for (int s = tid; s < total; s += TPB) {
        int row = s / H;
        int k   = s - row * H;
        int g   = row / H;
        int j   = row - g * H;
        float v = Whh[s];
        if (Wih) v += Wih[s];
        Ws[k * (4 * H) + j * 4 + g] = v;
    }
}

template<int H>
__device__ __forceinline__ void load_bias(ull* __restrict__ Bpk,
                                          const float* __restrict__ bih,
                                          const float* __restrict__ bhh, int tid)
{
    for (int j = tid; j < H; j += TPB) {
        Bpk[j * 2 + 0] = pk2(bih[j] + bhh[j],             bih[H + j] + bhh[H + j]);
        Bpk[j * 2 + 1] = pk2(bih[2*H + j] + bhh[2*H + j], bih[3*H + j] + bhh[3*H + j]);
    }
}

template<int H>
__device__ __forceinline__ void load_ih(ull* __restrict__ Ipk,
                                        const float* __restrict__ Wih, int tid)
{
    for (int t = tid; t < 2 * H; t += TPB) {
        int j = t >> 1, inp = t & 1;
        Ipk[(j * 2 + inp) * 2 + 0] = pk2(Wih[(0*H + j) * 2 + inp], Wih[(1*H + j) * 2 + inp]);
        Ipk[(j * 2 + inp) * 2 + 1] = pk2(Wih[(2*H + j) * 2 + inp], Wih[(3*H + j) * 2 + inp]);
    }
}

// ---------------- gate matmul: gates += h @ W^T (dup'd h, zero movs) ----------------
template<int H, int NH>
__device__ __forceinline__ void gates_mm(const float* __restrict__ Ws,
                                         const float* __restrict__ hb,   // Hs+HOFF*HROW+bcol*2
                                         int j0,
                                         ull (&aif)[NH][4], ull (&ago)[NH][4])
{
    const float* wb = Ws + j0 * 4;
    #pragma unroll 4
    for (int k = 0; k < H; k++) {
        ulonglong2 h01 = *(const ulonglong2*)(hb + k * HROW);       // (h0,h0),(h1,h1)
        ulonglong2 h23 = *(const ulonglong2*)(hb + k * HROW + 4);   // (h2,h2),(h3,h3)
        #pragma unroll
        for (int i = 0; i < NH; i++) {
            ulonglong2 w = *(const ulonglong2*)(wb + k * (4 * H) + i * 4);
            aif[i][0] = fma2(w.x, h01.x, aif[i][0]);
            ago[i][0] = fma2(w.y, h01.x, ago[i][0]);
            aif[i][1] = fma2(w.x, h01.y, aif[i][1]);
            ago[i][1] = fma2(w.y, h01.y, ago[i][1]);
            aif[i][2] = fma2(w.x, h23.x, aif[i][2]);
            ago[i][2] = fma2(w.y, h23.x, ago[i][2]);
            aif[i][3] = fma2(w.x, h23.y, aif[i][3]);
            ago[i][3] = fma2(w.y, h23.y, ago[i][3]);
        }
    }
}

// ---------------- activations + dup'd h store ----------------
template<int NH>
__device__ __forceinline__ void act_update(ull (&aif)[NH][4], ull (&ago)[NH][4],
                                           float (&cr)[NH][4],
                                           float* __restrict__ Hw)  // Hs+(HOFF+j0)*HROW+bcol*2
{
    #pragma unroll
    for (int i = 0; i < NH; i++) {
        float hn[4];
        #pragma unroll
        for (int b = 0; b < 4; b++) {
            float2 sif = upk(aif[i][b]);
            float2 sgo = upk(ago[i][b]);
            float ig = sigm(sif.x);
            float fg = sigm(sif.y);
            float gg = tanh_(sgo.x);
            float og = sigm(sgo.y);
            float cn = fmaf(fg, cr[i][b], ig * gg);
            cr[i][b] = cn;
            hn[b] = og * tanh_(cn);
        }
        *(float4*)(Hw + i * HROW + 0) = make_float4(hn[0], hn[0], hn[1], hn[1]);
        *(float4*)(Hw + i * HROW + 4) = make_float4(hn[2], hn[2], hn[3], hn[3]);
    }
}

// ---------------- input-driven LSTM phase (cent / enc), group-local sync ----------------
template<int H, int NH, int HOFF, int T>
__device__ __forceinline__ void lstm_io_phase(float* __restrict__ S,
                                              const float* __restrict__ xsrc, int xstride,
                                              int B, int bbase,
                                              int g, int tid_g, int j0, int bcol)
{
    float* Ws  = S + WS_OFF;
    float* Cs  = S + CS_OFF;
    float* Hs  = S + HS_OFF;
    ull*   Xs2 = (ull*)(S + XS_OFF);
    ull*   Bpk = (ull*)(S + BPK_OFF);
    ull*   Ipk = (ull*)(S + IPK_OFF);

    float cr[NH][4];
    #pragma unroll
    for (int i = 0; i < NH; i++)
        #pragma unroll
        for (int b = 0; b < 4; b++) cr[i][b] = 0.0f;

    ull bif[NH], bgo[NH], wif0[NH], wif1[NH], wgo0[NH], wgo1[NH];
    #pragma unroll
    for (int i = 0; i < NH; i++) {
        bif[i]  = Bpk[(j0 + i) * 2 + 0];
        bgo[i]  = Bpk[(j0 + i) * 2 + 1];
        wif0[i] = Ipk[((j0 + i) * 2 + 0) * 2 + 0];
        wgo0[i] = Ipk[((j0 + i) * 2 + 0) * 2 + 1];
        wif1[i] = Ipk[((j0 + i) * 2 + 1) * 2 + 0];
        wgo1[i] = Ipk[((j0 + i) * 2 + 1) * 2 + 1];
    }

    const float* hb = Hs + HOFF * HROW + bcol * 2;
    float*       Hw = Hs + (HOFF + j0) * HROW + bcol * 2;

    bool stager = (tid_g < GB);
    int  bstage = g * GB + tid_g;                 // batch col this thread stages
    int  bb = bbase + bstage; if (bb >= B) bb = B - 1;

    for (int t = 0; t < T; t++) {
        float2 xn;
        bool st = stager && (t + 1 < T);
        if (st)
            xn = *(const float2*)&xsrc[(size_t)bb * xstride + (size_t)(t + 1) * 2];

        ull aif[NH][4], ago[NH][4];
        #pragma unroll
        for (int b = 0; b < 4; b++) {
            ull x0 = Xs2[2 * (bcol + b) + 0];
            ull x1 = Xs2[2 * (bcol + b) + 1];
            #pragma unroll
            for (int i = 0; i < NH; i++) {
                aif[i][b] = fma2(wif0[i], x0, fma2(wif1[i], x1, bif[i]));
                ago[i][b] = fma2(wgo0[i], x0, fma2(wgo1[i], x1, bgo[i]));
            }
        }
        gates_mm<H, NH>(Ws, hb, j0, aif, ago);
        gbar(g);                                  // group's h/x reads done
        act_update<NH>(aif, ago, cr, Hw);
        if (st) {
            Xs2[2 * bstage + 0] = pk2(xn.x, xn.x);
            Xs2[2 * bstage + 1] = pk2(xn.y, xn.y);
        }
        gbar(g);                                  // group's new h/x visible
    }

    // stage final c for the decoder
    #pragma unroll
    for (int i = 0; i < NH; i++)
        #pragma unroll
        for (int b = 0; b < 4; b++)
            Cs[(HOFF + j0 + i) * BT + bcol + b] = cr[i][b];
}

// ---------------- main fused kernel ----------------
__global__ void __launch_bounds__(TPB, 1)
lstm_fused_kernel(const float* __restrict__ traj,   // [B,20,2]
                  const float* __restrict__ cl,     // [B,100,2]
                  const float* __restrict__ Wih_c, const float* __restrict__ Whh_c,
                  const float* __restrict__ bih_c, const float* __restrict__ bhh_c,
                  const float* __restrict__ Wih_e, const float* __restrict__ Whh_e,
                  const float* __restrict__ bih_e, const float* __restrict__ bhh_e,
                  const float* __restrict__ Wih_d, const float* __restrict__ Whh_d,
                  const float* __restrict__ bih_d, const float* __restrict__ bhh_d,
                  const float* __restrict__ W_emb, const float* __restrict__ b_emb,
                  float* __restrict__ out, int B)
{
    extern __shared__ float S[];
    int tid   = threadIdx.x;
    int bbase = blockIdx.x * BT;

    int g     = tid >> 7;        // warpgroup 0..3 (owns batch cols [16g,16g+16))
    int tid_g = tid & 127;
    int hg    = tid_g >> 2;      // hidden group 0..31
    int bg    = tid_g & 3;       // batch subgroup 0..3
    int bcol  = g * GB + bg * 4; // first of this thread's 4 batch cols

    float*  Ws   = S + WS_OFF;
    float*  Cs   = S + CS_OFF;
    float*  Hs   = S + HS_OFF;
    ull*    Xs2  = (ull*)(S + XS_OFF);
    ull*    Bpk  = (ull*)(S + BPK_OFF);
    float2* Wemb = (float2*)(S + WEMB_OFF);
    float2* Bemb = (float2*)(S + BEMB_OFF);

    // zero dup'd h (initial states)
    for (int s = tid; s < 96 * HROW; s += TPB) Hs[s] = 0.0f;

    int bbc = bbase + tid; if (bbc >= B) bbc = B - 1;

    // ---- phase 1: centerline LSTM (H=32, NH=1) -> rows 64..95 ----
    load_W<32>(Ws, Whh_c, nullptr, tid);
    load_bias<32>(Bpk, bih_c, bhh_c, tid);
    load_ih<32>((ull*)(S + IPK_OFF), Wih_c, tid);
    if (tid < BT) {
        float2 x = *(const float2*)&cl[(size_t)bbc * 200];
        Xs2[2 * tid + 0] = pk2(x.x, x.x);
        Xs2[2 * tid + 1] = pk2(x.y, x.y);
    }
    __syncthreads();
    __nanosleep((unsigned)(g * 400));            // skew groups -> MUFU/fma overlap
    lstm_io_phase<32, 1, 64, 100>(S, cl, 200, B, bbase, g, tid_g, hg * 1, bcol);
    __syncthreads();

    // ---- phase 2: encoder LSTM (H=64, NH=2) -> rows 0..63 ----
    load_W<64>(Ws, Whh_e, nullptr, tid);
    load_bias<64>(Bpk, bih_e, bhh_e, tid);
    load_ih<64>((ull*)(S + IPK_OFF), Wih_e, tid);
    if (tid < BT) {
        float2 x = *(const float2*)&traj[(size_t)bbc * 40];
        Xs2[2 * tid + 0] = pk2(x.x, x.x);
        Xs2[2 * tid + 1] = pk2(x.y, x.y);
    }
    __syncthreads();
    __nanosleep((unsigned)(g * 600));
    lstm_io_phase<64, 2, 0, 20>(S, traj, 40, B, bbase, g, tid_g, hg * 2, bcol);
    __syncthreads();

    // ---- phase 3: decoder (H=96, NH=3), x == h so Wih+Whh fold ----
    {
        constexpr int NH = 3;
        int j0 = hg * NH;

        // read c BEFORE load_W<96> clobbers the aliased Cs region
        float cr[NH][4];
        #pragma unroll
        for (int i = 0; i < NH; i++)
            #pragma unroll
            for (int b = 0; b < 4; b++)
                cr[i][b] = Cs[(j0 + i) * BT + bcol + b];
        __syncthreads();

        load_W<96>(Ws, Whh_d, Wih_d, tid);
        load_bias<96>(Bpk, bih_d, bhh_d, tid);
        for (int k = tid; k < 96; k += TPB) Wemb[k] = make_float2(W_emb[k], W_emb[96 + k]);
        if (tid == 0) *Bemb = make_float2(b_emb[0], b_emb[1]);
        __syncthreads();
        __nanosleep((unsigned)(g * 700));

        ull bif[NH], bgo[NH];
        #pragma unroll
        for (int i = 0; i < NH; i++) {
            bif[i] = Bpk[(j0 + i) * 2 + 0];
            bgo[i] = Bpk[(j0 + i) * 2 + 1];
        }

        const float* hb = Hs + bcol * 2;
        float*       Hw = Hs + j0 * HROW + bcol * 2;
        int bproj = g * GB + tid_g;              // for tid_g<16: projected batch col

        for (int t = 0; t < 30; t++) {
            ull aif[NH][4], ago[NH][4];
            #pragma unroll
            for (int i = 0; i < NH; i++)
                #pragma unroll
                for (int b = 0; b < 4; b++) { aif[i][b] = bif[i]; ago[i][b] = bgo[i]; }

            gates_mm<96, NH>(Ws, hb, j0, aif, ago);
            gbar(g);                             // group's h reads done
            act_update<NH>(aif, ago, cr, Hw);
            gbar(g);                             // group's new h visible

            // projection for this group's 16 batch cols (reads only, safe to
            // overlap the group's next-step gates which also only read)
            if (tid_g < GB) {
                float2 acc = *Bemb;
                #pragma unroll 8
                for (int k = 0; k < 96; k++) {
                    float  h = Hs[k * HROW + bproj * 2];   // dup'd, take lo
                    float2 w = Wemb[k];
                    acc.x = fmaf(h, w.x, acc.x);
                    acc.y = fmaf(h, w.y, acc.y);
                }
                int bb = bbase + bproj;
                if (bb < B) *(float2*)&out[(size_t)(bb * 30 + t) * 2] = acc;
            }
        }
    }
}

extern "C" void kernel_launch(void* const* d_in, const int* in_sizes, int n_in,
                              void* d_out, int out_size)
{
    const float* traj  = (const float*)d_in[0];
    const float* cl    = (const float*)d_in[1];
    const float* Wih_c = (const float*)d_in[2];
    const float* Whh_c = (const float*)d_in[3];
    const float* bih_c = (const float*)d_in[4];
    const float* bhh_c = (const float*)d_in[5];
    const float* Wih_e = (const float*)d_in[6];
    const float* Whh_e = (const float*)d_in[7];
    const float* bih_e = (const float*)d_in[8];
    const float* bhh_e = (const float*)d_in[9];
    const float* Wih_d = (const float*)d_in[10];
    const float* Whh_d = (const float*)d_in[11];
    const float* bih_d = (const float*)d_in[12];
    const float* bhh_d = (const float*)d_in[13];
    const float* W_emb = (const float*)d_in[14];
    const float* b_emb = (const float*)d_in[15];

    int B = in_sizes[0] / 40;
    int grid = (B + BT - 1) / BT;

    cudaFuncSetAttribute(lstm_fused_kernel,
                         cudaFuncAttributeMaxDynamicSharedMemorySize, SMEM_BYTES);
    lstm_fused_kernel<<<grid, TPB, SMEM_BYTES>>>(
        traj, cl, Wih_c, Whh_c, bih_c, bhh_c,
        Wih_e, Whh_e, bih_e, bhh_e,
        Wih_d, Whh_d, bih_d, bhh_d,
        W_emb, b_emb, (float*)d_out, B);
}

// round 5
// speedup vs baseline: 1.5602x; 1.3261x over previous
#include <cuda_runtime.h>

// Fused 3-phase LSTM (cent H=32 x100, enc H=64 x20, dec H=96 x30).
// R5 = R1's exact inner loops + new sync topology:
//  - 2 independent 256-thread groups, each owning 32 batch columns end-to-end,
//    synced ONLY by group-local named barriers -> group A's MUFU activation
//    burst overlaps group B's FFMA2 stream on every SMSP.
//  - anti-phase schedule: group0 cent->enc, group1 enc->cent.
//  - double-buffered h/x: ONE barrier per recurrence step.

#define TPB  512
#define BT   64
#define GBT  32      // batch columns per group

typedef unsigned long long ull;

// ---------------- packed f32x2 helpers ----------------
__device__ __forceinline__ ull pk2(float lo, float hi) {
    ull r; asm("mov.b64 %0, {%1, %2};" : "=l"(r) : "f"(lo), "f"(hi)); return r;
}
__device__ __forceinline__ ull dup2(float x) {
    ull r; asm("mov.b64 %0, {%1, %1};" : "=l"(r) : "f"(x)); return r;
}
__device__ __forceinline__ ull fma2(ull a, ull b, ull c) {
    ull d; asm("fma.rn.f32x2 %0, %1, %2, %3;" : "=l"(d) : "l"(a), "l"(b), "l"(c)); return d;
}
__device__ __forceinline__ float2 upk(ull a) {
    float lo, hi; asm("mov.b64 {%0, %1}, %2;" : "=f"(lo), "=f"(hi) : "l"(a));
    return make_float2(lo, hi);
}

// ---------------- fast activations (ex2-based, proven 7e-7 rel err) ----------------
__device__ __forceinline__ float fex2(float x){ float r; asm("ex2.approx.f32 %0, %1;" : "=f"(r) : "f"(x)); return r; }
__device__ __forceinline__ float frcp(float x){ float r; asm("rcp.approx.f32 %0, %1;" : "=f"(r) : "f"(x)); return r; }
__device__ __forceinline__ float sigm(float x){
    return frcp(1.0f + fex2(-1.4426950408889634f * x));
}
__device__ __forceinline__ float tanh_(float x){
    return fmaf(2.0f, sigm(2.0f * x), -1.0f);
}

// ---------------- group-local named barrier (256 threads) ----------------
__device__ __forceinline__ void gbar(int g) {
    asm volatile("bar.sync %0, %1;" :: "r"(g + 1), "r"(256) : "memory");
}

// ---------------- SMEM layout (float offsets) ----------------
// Phases: WS_C + WS_E live together; WS_D (36864) is staged AFTER both phases
// finish and clobbers [0,36864) including Cs (c is read into regs first).
#define WS_D_OFF  0        // decoder weights [0,36864)
#define WS_C_OFF  0        // cent weights   [0,4096)
#define WS_E_OFF  4096     // enc weights    [4096,20480)
#define CS_OFF    20480    // c staging [96][64] = 6144 -> [20480,26624)
#define HS_OFF    36864    // h state: 2 buffers x [96][64] = 2*6144
#define XS_OFF    49152    // dup'd x: 2 buffers x 128 ull = 512 floats
#define BPKC_OFF  49664    // cent bias:  64 ull
#define IPKC_OFF  49792    // cent Wih:  128 ull
#define BPKE_OFF  50048    // enc bias:  128 ull
#define IPKE_OFF  50304    // enc Wih:   256 ull
#define BPKD_OFF  50816    // dec bias:  192 ull
#define WEMB_OFF  51200    // 96 float2
#define BEMB_OFF  51392
#define SMEM_FLOATS 51396
#define SMEM_BYTES  (SMEM_FLOATS * 4)

// ---------------- weight/bias staging (CTA-wide) ----------------
template<int H>
__device__ __forceinline__ void load_W(float* __restrict__ Ws,
                                       const float* __restrict__ Whh,
                                       const float* __restrict__ Wih, int tid)
{
    constexpr int total = 4 * H * H;
    for (int s = tid; s < total; s += TPB) {
        int row = s / H;
        int k   = s - row * H;
        int g   = row / H;
        int j   = row - g * H;
        float v = Whh[s];
        if (Wih) v += Wih[s];
        Ws[k * (4 * H) + j * 4 + g] = v;
    }
}

template<int H>
__device__ __forceinline__ void load_bias(ull* __restrict__ Bpk,
                                          const float* __restrict__ bih,
                                          const float* __restrict__ bhh, int tid)
{
    for (int j = tid; j < H; j += TPB) {
        Bpk[j * 2 + 0] = pk2(bih[j] + bhh[j],             bih[H + j] + bhh[H + j]);
        Bpk[j * 2 + 1] = pk2(bih[2*H + j] + bhh[2*H + j], bih[3*H + j] + bhh[3*H + j]);
    }
}

template<int H>
__device__ __forceinline__ void load_ih(ull* __restrict__ Ipk,
                                        const float* __restrict__ Wih, int tid)
{
    for (int t = tid; t < 2 * H; t += TPB) {
        int j = t >> 1, inp = t & 1;
        Ipk[(j * 2 + inp) * 2 + 0] = pk2(Wih[(0*H + j) * 2 + inp], Wih[(1*H + j) * 2 + inp]);
        Ipk[(j * 2 + inp) * 2 + 1] = pk2(Wih[(2*H + j) * 2 + inp], Wih[(3*H + j) * 2 + inp]);
    }
}

// ---------------- gate matmul: gates += h @ W^T (R1's exact loop) ----------------
template<int H, int NH, int NB>
__device__ __forceinline__ void gates_mm(const float* __restrict__ Ws,
                                         const float* __restrict__ hbase, // Hc+HOFF*BT+bcol
                                         int j0,
                                         ull (&aif)[NH][NB], ull (&ago)[NH][NB])
{
    const float* wb = Ws + j0 * 4;
    #pragma unroll 4
    for (int k = 0; k < H; k++) {
        ull hp[NB];
        if constexpr (NB == 4) {
            float4 hv = *(const float4*)(hbase + k * BT);
            hp[0] = dup2(hv.x); hp[1] = dup2(hv.y); hp[2] = dup2(hv.z); hp[3] = dup2(hv.w);
        } else {
            float2 hv = *(const float2*)(hbase + k * BT);
            hp[0] = dup2(hv.x); hp[1] = dup2(hv.y);
        }
        #pragma unroll
        for (int i = 0; i < NH; i++) {
            ulonglong2 w = *(const ulonglong2*)(wb + k * (4 * H) + i * 4);
            #pragma unroll
            for (int b = 0; b < NB; b++) {
                aif[i][b] = fma2(w.x, hp[b], aif[i][b]);
                ago[i][b] = fma2(w.y, hp[b], ago[i][b]);
            }
        }
    }
}

// ---------------- activations + h store ----------------
template<int NH, int NB>
__device__ __forceinline__ void act_update(ull (&aif)[NH][NB], ull (&ago)[NH][NB],
                                           float (&cr)[NH][NB],
                                           float* __restrict__ Hw) // Hn+(HOFF+j0)*BT+bcol
{
    #pragma unroll
    for (int i = 0; i < NH; i++) {
        float hn[NB];
        #pragma unroll
        for (int b = 0; b < NB; b++) {
            float2 sif = upk(aif[i][b]);
            float2 sgo = upk(ago[i][b]);
            float ig = sigm(sif.x);
            float fg = sigm(sif.y);
            float gg = tanh_(sgo.x);
            float og = sigm(sgo.y);
            float cn = fmaf(fg, cr[i][b], ig * gg);
            cr[i][b] = cn;
            hn[b] = og * tanh_(cn);
        }
        if constexpr (NB == 4)
            *(float4*)(Hw + i * BT) = make_float4(hn[0], hn[1], hn[2], hn[3]);
        else
            *(float2*)(Hw + i * BT) = make_float2(hn[0], hn[1]);
    }
}

// ---------------- one input-driven LSTM phase, group-local ----------------
template<int H, int NH, int NB, int HOFF, int T>
__device__ __forceinline__ void lstm_phase(float* __restrict__ S,
                                           const float* __restrict__ xsrc, int xstride,
                                           int B, int bbase, int g, int tid_g,
                                           int wsOff, int bpkOff, int ipkOff)
{
    constexpr int BG = GBT / NB;
    static_assert((H / NH) * BG == 256, "group thread map");
    int hg = tid_g / BG, bg = tid_g % BG;
    int j0 = hg * NH, bcol = g * GBT + bg * NB;

    float* Ws = S + wsOff;
    float* Cs = S + CS_OFF;
    float* H0 = S + HS_OFF;  float* H1 = H0 + 6144;
    ull*   X0 = (ull*)(S + XS_OFF); ull* X1 = X0 + 128;
    ull*   Bpk = (ull*)(S + bpkOff);
    ull*   Ipk = (ull*)(S + ipkOff);

    float cr[NH][NB];
    #pragma unroll
    for (int i = 0; i < NH; i++)
        #pragma unroll
        for (int b = 0; b < NB; b++) cr[i][b] = 0.0f;

    ull bif[NH], bgo[NH], wif0[NH], wif1[NH], wgo0[NH], wgo1[NH];
    #pragma unroll
    for (int i = 0; i < NH; i++) {
        bif[i]  = Bpk[(j0 + i) * 2 + 0];
        bgo[i]  = Bpk[(j0 + i) * 2 + 1];
        wif0[i] = Ipk[((j0 + i) * 2 + 0) * 2 + 0];
        wgo0[i] = Ipk[((j0 + i) * 2 + 0) * 2 + 1];
        wif1[i] = Ipk[((j0 + i) * 2 + 1) * 2 + 0];
        wgo1[i] = Ipk[((j0 + i) * 2 + 1) * 2 + 1];
    }

    // initial x stage (group-local; 32 stager threads)
    bool stager = (tid_g < GBT);
    int  scol = g * GBT + tid_g;
    int  bb = bbase + scol; if (bb >= B) bb = B - 1;
    if (stager) {
        float2 x = *(const float2*)&xsrc[(size_t)bb * xstride];
        X0[2 * scol + 0] = pk2(x.x, x.x);
        X0[2 * scol + 1] = pk2(x.y, x.y);
    }
    gbar(g);

    float* Hc = H0; float* Hn = H1;
    ull*   Xc = X0; ull*   Xn = X1;

    for (int t = 0; t < T; t++) {
        float2 xnv;
        bool st = stager && (t + 1 < T);
        if (st)   // prefetch next x early; LDG hides under gates_mm
            xnv = *(const float2*)&xsrc[(size_t)bb * xstride + (size_t)(t + 1) * 2];

        ull aif[NH][NB], ago[NH][NB];
        #pragma unroll
        for (int b = 0; b < NB; b++) {
            ull xa = Xc[2 * (bcol + b) + 0];
            ull xb = Xc[2 * (bcol + b) + 1];
            #pragma unroll
            for (int i = 0; i < NH; i++) {
                aif[i][b] = fma2(wif0[i], xa, fma2(wif1[i], xb, bif[i]));
                ago[i][b] = fma2(wgo0[i], xa, fma2(wgo1[i], xb, bgo[i]));
            }
        }
        gates_mm<H, NH, NB>(Ws, Hc + HOFF * BT + bcol, j0, aif, ago);
        act_update<NH, NB>(aif, ago, cr, Hn + (HOFF + j0) * BT + bcol);
        if (st) {
            Xn[2 * scol + 0] = pk2(xnv.x, xnv.x);
            Xn[2 * scol + 1] = pk2(xnv.y, xnv.y);
        }
        gbar(g);   // one barrier per step (double-buffered h/x)
        { float* tf = Hc; Hc = Hn; Hn = tf; }
        { ull*  tx = Xc; Xc = Xn; Xn = tx; }
    }
    // T even for all phases -> final h lands in H0 (decoder's read buffer)

    // stage final c for the decoder
    #pragma unroll
    for (int i = 0; i < NH; i++)
        #pragma unroll
        for (int b = 0; b < NB; b++)
            Cs[(HOFF + j0 + i) * BT + bcol + b] = cr[i][b];
}

// ---------------- main fused kernel ----------------
__global__ void __launch_bounds__(TPB, 1)
lstm_fused_kernel(const float* __restrict__ traj,   // [B,20,2]
                  const float* __restrict__ cl,     // [B,100,2]
                  const float* __restrict__ Wih_c, const float* __restrict__ Whh_c,
                  const float* __restrict__ bih_c, const float* __restrict__ bhh_c,
                  const float* __restrict__ Wih_e, const float* __restrict__ Whh_e,
                  const float* __restrict__ bih_e, const float* __restrict__ bhh_e,
                  const float* __restrict__ Wih_d, const float* __restrict__ Whh_d,
                  const float* __restrict__ bih_d, const float* __restrict__ bhh_d,
                  const float* __restrict__ W_emb, const float* __restrict__ b_emb,
                  float* __restrict__ out, int B)
{
    extern __shared__ float S[];
    int tid   = threadIdx.x;
    int bbase = blockIdx.x * BT;
    int g     = tid >> 8;        // group 0/1 (owns batch cols [32g, 32g+32))
    int tid_g = tid & 255;

    float*  H0   = S + HS_OFF;
    float*  Cs   = S + CS_OFF;
    ull*    BpkD = (ull*)(S + BPKD_OFF);
    float2* Wemb = (float2*)(S + WEMB_OFF);
    float2* Bemb = (float2*)(S + BEMB_OFF);

    // zero h buffer 0 (initial states for both phases; H1 is written before read)
    for (int s = tid; s < 6144; s += TPB) H0[s] = 0.0f;

    // stage BOTH phases' weights/biases up front (CTA-wide)
    load_W<32>(S + WS_C_OFF, Whh_c, nullptr, tid);
    load_W<64>(S + WS_E_OFF, Whh_e, nullptr, tid);
    load_bias<32>((ull*)(S + BPKC_OFF), bih_c, bhh_c, tid);
    load_ih<32>((ull*)(S + IPKC_OFF), Wih_c, tid);
    load_bias<64>((ull*)(S + BPKE_OFF), bih_e, bhh_e, tid);
    load_ih<64>((ull*)(S + IPKE_OFF), Wih_e, tid);
    __syncthreads();

    // anti-phase schedule: g0 cent->enc, g1 enc->cent (structural MUFU/FMA overlap)
    if (g == 0) {
        lstm_phase<32, 2, 2, 64, 100>(S, cl,   200, B, bbase, g, tid_g, WS_C_OFF, BPKC_OFF, IPKC_OFF);
        lstm_phase<64, 2, 4,  0,  20>(S, traj,  40, B, bbase, g, tid_g, WS_E_OFF, BPKE_OFF, IPKE_OFF);
    } else {
        lstm_phase<64, 2, 4,  0,  20>(S, traj,  40, B, bbase, g, tid_g, WS_E_OFF, BPKE_OFF, IPKE_OFF);
        lstm_phase<32, 2, 2, 64, 100>(S, cl,   200, B, bbase, g, tid_g, WS_C_OFF, BPKC_OFF, IPKC_OFF);
    }
    __syncthreads();

    // ---- decoder (H=96), x == h so Wih+Whh fold into one matrix ----
    {
        constexpr int NH = 3, NB = 4, BG = GBT / NB;   // 32 hidden groups x 8 batch groups
        int hg = tid_g / BG, bg = tid_g % BG;
        int j0 = hg * NH, bcol = g * GBT + bg * NB;

        // read c BEFORE load_W<96> clobbers the aliased Cs region
        float cr[NH][NB];
        #pragma unroll
        for (int i = 0; i < NH; i++)
            #pragma unroll
            for (int b = 0; b < NB; b++)
                cr[i][b] = Cs[(j0 + i) * BT + bcol + b];
        __syncthreads();

        load_W<96>(S + WS_D_OFF, Whh_d, Wih_d, tid);
        load_bias<96>(BpkD, bih_d, bhh_d, tid);
        for (int k = tid; k < 96; k += TPB) Wemb[k] = make_float2(W_emb[k], W_emb[96 + k]);
        if (tid == 0) *Bemb = make_float2(b_emb[0], b_emb[1]);
        __syncthreads();
        if (g) __nanosleep(900);   // half-step skew -> groups' MUFU/fma interleave

        const float* Ws = S + WS_D_OFF;
        ull bif[NH], bgo[NH];
        #pragma unroll
        for (int i = 0; i < NH; i++) {
            bif[i] = BpkD[(j0 + i) * 2 + 0];
            bgo[i] = BpkD[(j0 + i) * 2 + 1];
        }

        float* Hc = S + HS_OFF;          // h0 = concat(enc, cent) in buffer 0
        float* Hn = S + HS_OFF + 6144;

        bool projer = (tid_g < GBT);
        int  pcol   = g * GBT + tid_g;   // projected batch col (tid_g<32)
        int  pb     = bbase + pcol;

        for (int t = 0; t < 30; t++) {
            ull aif[NH][NB], ago[NH][NB];
            #pragma unroll
            for (int i = 0; i < NH; i++)
                #pragma unroll
                for (int b = 0; b < NB; b++) { aif[i][b] = bif[i]; ago[i][b] = bgo[i]; }

            gates_mm<96, NH, NB>(Ws, Hc + bcol, j0, aif, ago);
            act_update<NH, NB>(aif, ago, cr, Hn + j0 * BT + bcol);
            gbar(g);                      // group's new h visible

            // projection: pos = h_new @ W_emb^T + b_emb (32 threads per group;
            // reads Hn only; next step's writes go to Hc -> no conflict)
            if (projer) {
                float2 acc = *Bemb;
                #pragma unroll 8
                for (int k = 0; k < 96; k++) {
                    float  h = Hn[k * BT + pcol];
                    float2 w = Wemb[k];
                    acc.x = fmaf(h, w.x, acc.x);
                    acc.y = fmaf(h, w.y, acc.y);
                }
                if (pb < B) *(float2*)&out[(size_t)(pb * 30 + t) * 2] = acc;
            }
            { float* tf = Hc; Hc = Hn; Hn = tf; }
        }
    }
}

extern "C" void kernel_launch(void* const* d_in, const int* in_sizes, int n_in,
                              void* d_out, int out_size)
{
    const float* traj  = (const float*)d_in[0];
    const float* cl    = (const float*)d_in[1];
    const float* Wih_c = (const float*)d_in[2];
    const float* Whh_c = (const float*)d_in[3];
    const float* bih_c = (const float*)d_in[4];
    const float* bhh_c = (const float*)d_in[5];
    const float* Wih_e = (const float*)d_in[6];
    const float* Whh_e = (const float*)d_in[7];
    const float* bih_e = (const float*)d_in[8];
    const float* bhh_e = (const float*)d_in[9];
    const float* Wih_d = (const float*)d_in[10];
    const float* Whh_d = (const float*)d_in[11];
    const float* bih_d = (const float*)d_in[12];
    const float* bhh_d = (const float*)d_in[13];
    const float* W_emb = (const float*)d_in[14];
    const float* b_emb = (const float*)d_in[15];

    int B = in_sizes[0] / 40;
    int grid = (B + BT - 1) / BT;

    cudaFuncSetAttribute(lstm_fused_kernel,
                         cudaFuncAttributeMaxDynamicSharedMemorySize, SMEM_BYTES);
    lstm_fused_kernel<<<grid, TPB, SMEM_BYTES>>>(
        traj, cl, Wih_c, Whh_c, bih_c, bhh_c,
        Wih_e, Whh_e, bih_e, bhh_e,
        Wih_d, Whh_d, bih_d, bhh_d,
        W_emb, b_emb, (float*)d_out, B);
}